// round 13
// baseline (speedup 1.0000x reference)
#include <cuda_runtime.h>
#include <cuda_fp16.h>
#include <cstdint>

#define NN   8192
#define IND  128
#define OUTD 64
#define NSPLIT 6               // uneven j-splits: tiles 43,43,43,43,42,42
#define TOTTILES 256           // 8192 / 32
#define JT 32                  // K tile
#define ITILE 128              // M rows per block
#define ASTR 40                // A row stride (fp16 elems)
#define BSTR 40                // B row stride

// smem elem offsets (fp16), double buffered. A = p fp16, B = W fp16 (1 term).
#define OFF_A(b)  ((b) * 5120)
#define OFF_B(b)  (10240 + (b) * 2560)
#define SMEM_ELEMS 15360
#define SMEM_BYTES (SMEM_ELEMS * 2)    // 30720 B

#define PSCALE 0.00390625f     // 2^-8: keeps p in fp16 range (exact scaling)

// static device scratch (no allocations allowed)
__device__ float g_Wh[(size_t)NN * OUTD];
__device__ float g_s1[NN];
__device__ float g_s2[NN];
__device__ __half g_WhT[(size_t)OUTD * NN];  // [d][j] fp16
__device__ float g_part[(size_t)NSPLIT * NN * OUTD];
__device__ float g_lp[(size_t)NSPLIT * NN];

__device__ __forceinline__ uint32_t smem_u32(const void* p) {
    return (uint32_t)__cvta_generic_to_shared(p);
}
__device__ __forceinline__ void ldsm_x4(uint32_t& r0, uint32_t& r1, uint32_t& r2, uint32_t& r3, uint32_t a) {
    asm volatile("ldmatrix.sync.aligned.m8n8.x4.shared.b16 {%0,%1,%2,%3}, [%4];"
                 : "=r"(r0), "=r"(r1), "=r"(r2), "=r"(r3) : "r"(a));
}
__device__ __forceinline__ void mma_f16(float* c, const uint32_t* A, uint32_t b0, uint32_t b1) {
    asm volatile(
        "mma.sync.aligned.m16n8k16.row.col.f32.f16.f16.f32 "
        "{%0,%1,%2,%3}, {%4,%5,%6,%7}, {%8,%9}, {%0,%1,%2,%3};"
        : "+f"(c[0]), "+f"(c[1]), "+f"(c[2]), "+f"(c[3])
        : "r"(A[0]), "r"(A[1]), "r"(A[2]), "r"(A[3]), "r"(b0), "r"(b1));
}

// ---------------------------------------------------------------------------
// K1: Wh = x@W (fp32, coalesced); s1/s2 = Wh@a halves
// ---------------------------------------------------------------------------
__global__ __launch_bounds__(128) void k1_proj(const float* __restrict__ x,
                                               const float* __restrict__ W,
                                               const float* __restrict__ a) {
    __shared__ float W_sm[IND][OUTD];
    __shared__ float x_sm[32][33];

    const int t  = threadIdx.x;
    const int i0 = blockIdx.x * 32;
    const int dl = t & 15;
    const int rl = t >> 4;

    {
        const float4* src = (const float4*)W;
        float4* dst = (float4*)&W_sm[0][0];
#pragma unroll
        for (int q = 0; q < 16; ++q) dst[t + 128 * q] = src[t + 128 * q];
    }

    float acc[4][4];
#pragma unroll
    for (int rr = 0; rr < 4; ++rr)
#pragma unroll
        for (int dd = 0; dd < 4; ++dd) acc[rr][dd] = 0.f;

    for (int k0 = 0; k0 < IND; k0 += 32) {
        __syncthreads();
#pragma unroll
        for (int q = 0; q < 8; ++q) {
            int idx = t + 128 * q;
            int r = idx >> 5, kk = idx & 31;
            x_sm[r][kk] = x[(size_t)(i0 + r) * IND + k0 + kk];
        }
        __syncthreads();
#pragma unroll
        for (int kk = 0; kk < 32; ++kk) {
            float4 w = *(const float4*)&W_sm[k0 + kk][dl * 4];
#pragma unroll
            for (int rr = 0; rr < 4; ++rr) {
                float xv = x_sm[rl * 4 + rr][kk];
                acc[rr][0] += xv * w.x;
                acc[rr][1] += xv * w.y;
                acc[rr][2] += xv * w.z;
                acc[rr][3] += xv * w.w;
            }
        }
    }

    const float* a1 = a;
    const float* a2 = a + OUTD;
#pragma unroll
    for (int rr = 0; rr < 4; ++rr) {
        int row = i0 + rl * 4 + rr;
        *(float4*)&g_Wh[(size_t)row * OUTD + dl * 4] =
            make_float4(acc[rr][0], acc[rr][1], acc[rr][2], acc[rr][3]);
        float4 av1 = *(const float4*)&a1[dl * 4];
        float4 av2 = *(const float4*)&a2[dl * 4];
        float v1 = acc[rr][0] * av1.x + acc[rr][1] * av1.y + acc[rr][2] * av1.z + acc[rr][3] * av1.w;
        float v2 = acc[rr][0] * av2.x + acc[rr][1] * av2.y + acc[rr][2] * av2.z + acc[rr][3] * av2.w;
#pragma unroll
        for (int o = 8; o >= 1; o >>= 1) {
            v1 += __shfl_xor_sync(0xffffffffu, v1, o, 16);
            v2 += __shfl_xor_sync(0xffffffffu, v2, o, 16);
        }
        if (dl == 0) { g_s1[row] = v1; g_s2[row] = v2; }
    }
}

// ---------------------------------------------------------------------------
// K1b: transpose Wh -> WhT fp16
// ---------------------------------------------------------------------------
__global__ __launch_bounds__(256) void k1b_transpose() {
    __shared__ float ts[64][68];
    const int t  = threadIdx.x;
    const int j0 = blockIdx.x * 64;

#pragma unroll
    for (int q = 0; q < 4; ++q) {
        int idx = t + 256 * q;
        int r = idx >> 4, c4 = (idx & 15) * 4;
        *(float4*)&ts[r][c4] = *(const float4*)&g_Wh[(size_t)(j0 + r) * OUTD + c4];
    }
    __syncthreads();

    const int d  = t >> 2;
    const int jq = (t & 3) * 16;
    uint32_t hi[8];
#pragma unroll
    for (int u = 0; u < 8; ++u) {
        float v0 = ts[jq + 2 * u][d];
        float v1 = ts[jq + 2 * u + 1][d];
        __half2 hh = __floats2half2_rn(v0, v1);
        hi[u] = *(uint32_t*)&hh;
    }
    __half* dh = g_WhT + (size_t)d * NN + j0 + jq;
    *(uint4*)dh       = make_uint4(hi[0], hi[1], hi[2], hi[3]);
    *(uint4*)(dh + 8) = make_uint4(hi[4], hi[5], hi[6], hi[7]);
}

// ---------------------------------------------------------------------------
// K2: software-pipelined, 256 threads / 8 warps (warp owns m16), fp16 1-term.
// A = p*2^-8 fp16; B = W fp16. Epilogue multiplies by 256.
// grid = (64, 6) = 384 blocks @ 3/SM single wave.
// ---------------------------------------------------------------------------
__global__ __launch_bounds__(256, 3) void k2_attn_mma(const int* __restrict__ adj) {
    extern __shared__ __half sm[];

    const int t     = threadIdx.x;
    const int wid   = t >> 5;
    const int lid   = t & 31;
    const int i0    = blockIdx.x * ITILE;
    const int split = blockIdx.y;

    const int base  = TOTTILES / NSPLIT;
    const int rem   = TOTTILES % NSPLIT;
    const int start = split * base + (split < rem ? split : rem);
    const int cnt   = base + (split < rem ? 1 : 0);
    const int js    = start * JT;

    // A-phase role: row = t>>1, 16-j half = (t&1)*16
    const int arow  = t >> 1;
    const int ahalf = (t & 1) * 16;
    const float s1v = g_s1[i0 + arow];
    const int* adjrow = adj + (size_t)(i0 + arow) * NN + js + ahalf;

    // B-phase role: row = t>>2, quarter = (t&3)*8
    const int bn = t >> 2, bk = (t & 3) * 8;
    const __half* bhp = g_WhT + (size_t)bn * NN + js + bk;

    float lacc = 0.f;
    float c[8][4];
#pragma unroll
    for (int nt = 0; nt < 8; ++nt)
#pragma unroll
        for (int q = 0; q < 4; ++q) c[nt][q] = 0.f;

    auto build = [&](int tl, int b, const int4* pa) {
        const int j0 = tl * JT;
        // B tile: one uint4 per thread
        *(uint4*)(sm + OFF_B(b) + bn * BSTR + bk) = *(const uint4*)(bhp + j0);
        // A tile: 16 p values (scaled by 2^-8), fp16
        const float4* s4p = (const float4*)(g_s2 + js + j0 + ahalf);
        __half* Ah = sm + OFF_A(b) + arow * ASTR + ahalf;
#pragma unroll
        for (int k = 0; k < 2; ++k) {
            int4   aA = pa[2 * k], aB = pa[2 * k + 1];
            float4 sA = s4p[2 * k], sB = s4p[2 * k + 1];
            float p0, p1, p2, p3, p4, p5, p6, p7, e;
            e = s1v + sA.x; e = fmaxf(e, 0.2f * e); p0 = aA.x ? __expf(e) : 0.f;
            e = s1v + sA.y; e = fmaxf(e, 0.2f * e); p1 = aA.y ? __expf(e) : 0.f;
            e = s1v + sA.z; e = fmaxf(e, 0.2f * e); p2 = aA.z ? __expf(e) : 0.f;
            e = s1v + sA.w; e = fmaxf(e, 0.2f * e); p3 = aA.w ? __expf(e) : 0.f;
            e = s1v + sB.x; e = fmaxf(e, 0.2f * e); p4 = aB.x ? __expf(e) : 0.f;
            e = s1v + sB.y; e = fmaxf(e, 0.2f * e); p5 = aB.y ? __expf(e) : 0.f;
            e = s1v + sB.z; e = fmaxf(e, 0.2f * e); p6 = aB.z ? __expf(e) : 0.f;
            e = s1v + sB.w; e = fmaxf(e, 0.2f * e); p7 = aB.w ? __expf(e) : 0.f;
            lacc += ((p0 + p1) + (p2 + p3)) + ((p4 + p5) + (p6 + p7));

            __half2 h01 = __floats2half2_rn(p0 * PSCALE, p1 * PSCALE);
            __half2 h23 = __floats2half2_rn(p2 * PSCALE, p3 * PSCALE);
            __half2 h45 = __floats2half2_rn(p4 * PSCALE, p5 * PSCALE);
            __half2 h67 = __floats2half2_rn(p6 * PSCALE, p7 * PSCALE);
            *(uint4*)(Ah + k * 8) = make_uint4(*(uint32_t*)&h01, *(uint32_t*)&h23,
                                               *(uint32_t*)&h45, *(uint32_t*)&h67);
        }
    };

    // prologue: build tile 0 into buffer 0
    {
        int4 pa[4];
#pragma unroll
        for (int q = 0; q < 4; ++q) pa[q] = ((const int4*)adjrow)[q];
        build(0, 0, pa);
    }
    __syncthreads();

    const uint32_t ROWB = ASTR * 2;   // 80 B
    // B lane mapping for ldsm_x4: 4 mats = 2 n-octets x 2 k-chunks
    const int bn_l = (lid & 7) + ((lid >> 4) << 3);
    const int bk_l = ((lid >> 3) & 1) * 8;

    for (int tile = 0; tile < cnt; ++tile) {
        const int cur = tile & 1, nb = cur ^ 1;

        int4 pa[4];
        if (tile + 1 < cnt) {
            const int4* src = (const int4*)(adjrow + (tile + 1) * JT);
#pragma unroll
            for (int q = 0; q < 4; ++q) pa[q] = src[q];
        }

        // ---- MMA on buffer cur: warp = m16 x n64 x k32, 1 term
        const uint32_t a0  = smem_u32(sm + OFF_A(cur) + (wid * 16 + (lid & 15)) * ASTR + (lid >> 4) * 8);
        const uint32_t b0a = smem_u32(sm + OFF_B(cur) + bn_l * BSTR + bk_l);
#pragma unroll
        for (int kt = 0; kt < 2; ++kt) {
            uint32_t Ah[4];
            ldsm_x4(Ah[0], Ah[1], Ah[2], Ah[3], a0 + kt * 32);
#pragma unroll
            for (int np = 0; np < 4; ++np) {
                uint32_t bh0, bh1, bh2, bh3;
                ldsm_x4(bh0, bh1, bh2, bh3, b0a + (uint32_t)(np * 16) * ROWB + kt * 32);
                mma_f16(c[2 * np],     Ah, bh0, bh1);
                mma_f16(c[2 * np + 1], Ah, bh2, bh3);
            }
        }

        // ---- build tile+1 into buffer nb
        if (tile + 1 < cnt) build(tile + 1, nb, pa);
        __syncthreads();
    }

    // l: the two half-row threads are adjacent lanes
    lacc += __shfl_xor_sync(0xffffffffu, lacc, 1);
    if ((t & 1) == 0) g_lp[(size_t)split * NN + i0 + arow] = lacc;

    // ---- epilogue: raw partials (undo 2^-8 scale)
    const int rbase = i0 + wid * 16 + (lid >> 2);
    const int cbase = 2 * (lid & 3);
#pragma unroll
    for (int nt = 0; nt < 8; ++nt) {
        const int col = nt * 8 + cbase;
        float* d0 = &g_part[((size_t)split * NN + rbase) * OUTD + col];
        float* d1 = &g_part[((size_t)split * NN + rbase + 8) * OUTD + col];
        *(float2*)d0 = make_float2(c[nt][0] * 256.f, c[nt][1] * 256.f);
        *(float2*)d1 = make_float2(c[nt][2] * 256.f, c[nt][3] * 256.f);
    }
}

// ---------------------------------------------------------------------------
// K3: reduce NSPLIT partials, normalize, ELU.
// ---------------------------------------------------------------------------
__global__ __launch_bounds__(128) void k3_reduce(float* __restrict__ out) {
    const int q   = blockIdx.x * 128 + threadIdx.x;
    const int row = q >> 4;
    const int c4  = (q & 15) * 4;

    float l = 0.f;
#pragma unroll
    for (int s = 0; s < NSPLIT; ++s) l += g_lp[(size_t)s * NN + row];
    const float inv = 1.0f / l;

    float4 acc = make_float4(0.f, 0.f, 0.f, 0.f);
#pragma unroll
    for (int s = 0; s < NSPLIT; ++s) {
        float4 v = *(const float4*)&g_part[((size_t)s * NN + row) * OUTD + c4];
        acc.x += v.x; acc.y += v.y; acc.z += v.z; acc.w += v.w;
    }
    acc.x *= inv; acc.y *= inv; acc.z *= inv; acc.w *= inv;
    acc.x = acc.x > 0.f ? acc.x : expm1f(acc.x);
    acc.y = acc.y > 0.f ? acc.y : expm1f(acc.y);
    acc.z = acc.z > 0.f ? acc.z : expm1f(acc.z);
    acc.w = acc.w > 0.f ? acc.w : expm1f(acc.w);
    *(float4*)&out[(size_t)row * OUTD + c4] = acc;
}

extern "C" void kernel_launch(void* const* d_in, const int* in_sizes, int n_in,
                              void* d_out, int out_size) {
    const float* x   = (const float*)d_in[0];
    const int*   adj = (const int*)d_in[1];
    const float* W   = (const float*)d_in[2];
    const float* a   = (const float*)d_in[3];
    float* out = (float*)d_out;

    cudaFuncSetAttribute(k2_attn_mma, cudaFuncAttributeMaxDynamicSharedMemorySize, SMEM_BYTES);

    k1_proj<<<256, 128>>>(x, W, a);
    k1b_transpose<<<NN / 64, 256>>>();
    k2_attn_mma<<<dim3(NN / ITILE, NSPLIT), 256, SMEM_BYTES>>>(adj);
    k3_reduce<<<(NN * OUTD / 4) / 128, 128>>>(out);
}

// round 15
// speedup vs baseline: 1.4571x; 1.4571x over previous
#include <cuda_runtime.h>
#include <cuda_fp16.h>
#include <cstdint>

#define NN   8192
#define IND  128
#define OUTD 64
#define NSPLIT 6               // uneven j-splits: tiles 43,43,43,43,42,42
#define TOTTILES 256           // 8192 / 32
#define JT 32                  // K tile
#define ITILE 128              // M rows per block
#define BSTR 40                // B row stride (fp16 elems)

// smem (halfs): B double buffer then s2 floats
#define OFF_B(b)  ((b) * 2560)
#define OFF_S2    5120                 // as float*, 1376 floats max
#define SMEM_BYTES (5120 * 2 + 1376 * 4 + 64)

#define LOG2E 1.4426950408889634f

// static device scratch (no allocations allowed)
__device__ float g_Wh[(size_t)NN * OUTD];
__device__ float g_s1[NN];
__device__ float g_s2[NN];
__device__ __half g_WhT[(size_t)OUTD * NN];  // [d][j] fp16
__device__ float g_part[(size_t)NSPLIT * NN * OUTD];
__device__ float g_lp[(size_t)NSPLIT * NN];

__device__ __forceinline__ uint32_t smem_u32(const void* p) {
    return (uint32_t)__cvta_generic_to_shared(p);
}
__device__ __forceinline__ void ldsm_x4(uint32_t& r0, uint32_t& r1, uint32_t& r2, uint32_t& r3, uint32_t a) {
    asm volatile("ldmatrix.sync.aligned.m8n8.x4.shared.b16 {%0,%1,%2,%3}, [%4];"
                 : "=r"(r0), "=r"(r1), "=r"(r2), "=r"(r3) : "r"(a));
}
__device__ __forceinline__ void mma_f16(float* c, const uint32_t* A, uint32_t b0, uint32_t b1) {
    asm volatile(
        "mma.sync.aligned.m16n8k16.row.col.f32.f16.f16.f32 "
        "{%0,%1,%2,%3}, {%4,%5,%6,%7}, {%8,%9}, {%0,%1,%2,%3};"
        : "+f"(c[0]), "+f"(c[1]), "+f"(c[2]), "+f"(c[3])
        : "r"(A[0]), "r"(A[1]), "r"(A[2]), "r"(A[3]), "r"(b0), "r"(b1));
}
__device__ __forceinline__ float ex2(float x) {
    float r; asm("ex2.approx.f32 %0, %1;" : "=f"(r) : "f"(x)); return r;
}
// compute two masked scaled-softmax numerators, pack to half2 (A-frag reg)
__device__ __forceinline__ uint32_t pcvt(float s1v, float2 s2, int2 m, float& lacc) {
    float e0 = s1v + s2.x; e0 = fmaxf(e0, 0.2f * e0);
    float e1 = s1v + s2.y; e1 = fmaxf(e1, 0.2f * e1);
    float p0 = m.x ? ex2(fmaf(e0, LOG2E, -8.f)) : 0.f;
    float p1 = m.y ? ex2(fmaf(e1, LOG2E, -8.f)) : 0.f;
    lacc += p0 + p1;
    __half2 h = __floats2half2_rn(p0, p1);
    return *(uint32_t*)&h;
}

// ---------------------------------------------------------------------------
// K1: Wh = x@W (fp32, coalesced); s1/s2 = Wh@a halves
// ---------------------------------------------------------------------------
__global__ __launch_bounds__(128) void k1_proj(const float* __restrict__ x,
                                               const float* __restrict__ W,
                                               const float* __restrict__ a) {
    __shared__ float W_sm[IND][OUTD];
    __shared__ float x_sm[32][33];

    const int t  = threadIdx.x;
    const int i0 = blockIdx.x * 32;
    const int dl = t & 15;
    const int rl = t >> 4;

    {
        const float4* src = (const float4*)W;
        float4* dst = (float4*)&W_sm[0][0];
#pragma unroll
        for (int q = 0; q < 16; ++q) dst[t + 128 * q] = src[t + 128 * q];
    }

    float acc[4][4];
#pragma unroll
    for (int rr = 0; rr < 4; ++rr)
#pragma unroll
        for (int dd = 0; dd < 4; ++dd) acc[rr][dd] = 0.f;

    for (int k0 = 0; k0 < IND; k0 += 32) {
        __syncthreads();
#pragma unroll
        for (int q = 0; q < 8; ++q) {
            int idx = t + 128 * q;
            int r = idx >> 5, kk = idx & 31;
            x_sm[r][kk] = x[(size_t)(i0 + r) * IND + k0 + kk];
        }
        __syncthreads();
#pragma unroll
        for (int kk = 0; kk < 32; ++kk) {
            float4 w = *(const float4*)&W_sm[k0 + kk][dl * 4];
#pragma unroll
            for (int rr = 0; rr < 4; ++rr) {
                float xv = x_sm[rl * 4 + rr][kk];
                acc[rr][0] += xv * w.x;
                acc[rr][1] += xv * w.y;
                acc[rr][2] += xv * w.z;
                acc[rr][3] += xv * w.w;
            }
        }
    }

    const float* a1 = a;
    const float* a2 = a + OUTD;
#pragma unroll
    for (int rr = 0; rr < 4; ++rr) {
        int row = i0 + rl * 4 + rr;
        *(float4*)&g_Wh[(size_t)row * OUTD + dl * 4] =
            make_float4(acc[rr][0], acc[rr][1], acc[rr][2], acc[rr][3]);
        float4 av1 = *(const float4*)&a1[dl * 4];
        float4 av2 = *(const float4*)&a2[dl * 4];
        float v1 = acc[rr][0] * av1.x + acc[rr][1] * av1.y + acc[rr][2] * av1.z + acc[rr][3] * av1.w;
        float v2 = acc[rr][0] * av2.x + acc[rr][1] * av2.y + acc[rr][2] * av2.z + acc[rr][3] * av2.w;
#pragma unroll
        for (int o = 8; o >= 1; o >>= 1) {
            v1 += __shfl_xor_sync(0xffffffffu, v1, o, 16);
            v2 += __shfl_xor_sync(0xffffffffu, v2, o, 16);
        }
        if (dl == 0) { g_s1[row] = v1; g_s2[row] = v2; }
    }
}

// ---------------------------------------------------------------------------
// K1b: transpose Wh -> WhT fp16
// ---------------------------------------------------------------------------
__global__ __launch_bounds__(256) void k1b_transpose() {
    __shared__ float ts[64][68];
    const int t  = threadIdx.x;
    const int j0 = blockIdx.x * 64;

#pragma unroll
    for (int q = 0; q < 4; ++q) {
        int idx = t + 256 * q;
        int r = idx >> 4, c4 = (idx & 15) * 4;
        *(float4*)&ts[r][c4] = *(const float4*)&g_Wh[(size_t)(j0 + r) * OUTD + c4];
    }
    __syncthreads();

    const int d  = t >> 2;
    const int jq = (t & 3) * 16;
    uint32_t hi[8];
#pragma unroll
    for (int u = 0; u < 8; ++u) {
        __half2 hh = __floats2half2_rn(ts[jq + 2 * u][d], ts[jq + 2 * u + 1][d]);
        hi[u] = *(uint32_t*)&hh;
    }
    __half* dh = g_WhT + (size_t)d * NN + j0 + jq;
    *(uint4*)dh       = make_uint4(hi[0], hi[1], hi[2], hi[3]);
    *(uint4*)(dh + 8) = make_uint4(hi[4], hi[5], hi[6], hi[7]);
}

// ---------------------------------------------------------------------------
// K2: fragment-direct A (p computed straight into mma A-frag regs), B via
// double-buffered smem + ldsm. 256 thr / 8 warps, warp owns m16.
// grid (64, 6) single wave.
// ---------------------------------------------------------------------------
__global__ __launch_bounds__(256, 3) void k2_attn_mma(const int* __restrict__ adj) {
    extern __shared__ __half sm[];
    float* s2s = (float*)(sm + OFF_S2);

    const int t     = threadIdx.x;
    const int wid   = t >> 5;
    const int lid   = t & 31;
    const int i0    = blockIdx.x * ITILE;
    const int split = blockIdx.y;

    const int base  = TOTTILES / NSPLIT;
    const int rem   = TOTTILES % NSPLIT;
    const int start = split * base + (split < rem ? split : rem);
    const int cnt   = base + (split < rem ? 1 : 0);
    const int js    = start * JT;

    // fragment lane mapping
    const int qr = lid >> 2;           // 0..7
    const int qc = (lid & 3) * 2;      // 0,2,4,6
    const int r0 = i0 + wid * 16 + qr;
    const int r1 = r0 + 8;
    const float s1v0 = g_s1[r0];
    const float s1v1 = g_s1[r1];
    const int* adjr0 = adj + (size_t)r0 * NN + js;
    const int* adjr1 = adj + (size_t)r1 * NN + js;

    // B-build role: all 256 threads, one uint4 (8 halfs) each -> full 64x32 tile
    const int bn = t >> 2, bk = (t & 3) * 8;
    const __half* bhp = g_WhT + (size_t)bn * NN + js + bk;

    // B ldsm lane mapping (proven): 4 mats = 2 n-octets x 2 k-chunks
    const int bn_l = (lid & 7) + ((lid >> 4) << 3);
    const int bk_l = ((lid >> 3) & 1) * 8;
    const uint32_t ROWB = BSTR * 2;    // 80 B

    float lacc0 = 0.f, lacc1 = 0.f;
    float c[8][4];
#pragma unroll
    for (int nt = 0; nt < 8; ++nt)
#pragma unroll
        for (int q = 0; q < 4; ++q) c[nt][q] = 0.f;

    // preload s2 segment into smem (cnt*32 <= 1376 floats)
    for (int idx = t; idx < cnt * JT; idx += 256) s2s[idx] = g_s2[js + idx];

    // prologue: B tile 0 into buffer 0; adj tile 0 into regs
    *(uint4*)(sm + OFF_B(0) + bn * BSTR + bk) = *(const uint4*)bhp;
    int2 m[8];
    {
        const int* p0 = adjr0 + qc;
        const int* p1 = adjr1 + qc;
        m[0] = *(const int2*)(p0);      m[1] = *(const int2*)(p0 + 8);
        m[2] = *(const int2*)(p1);      m[3] = *(const int2*)(p1 + 8);
        m[4] = *(const int2*)(p0 + 16); m[5] = *(const int2*)(p0 + 24);
        m[6] = *(const int2*)(p1 + 16); m[7] = *(const int2*)(p1 + 24);
    }
    __syncthreads();

    for (int tile = 0; tile < cnt; ++tile) {
        const int cur = tile & 1, nb = cur ^ 1;
        const int j0 = tile * JT;
        const bool more = (tile + 1 < cnt);

        // B next tile -> regs
        uint4 bnext;
        if (more) bnext = *(const uint4*)(bhp + (tile + 1) * JT);

        // ---- A fragments from prefetched adj + smem s2
        float2 s2_0  = *(const float2*)&s2s[j0 + qc];
        float2 s2_8  = *(const float2*)&s2s[j0 + qc + 8];
        float2 s2_16 = *(const float2*)&s2s[j0 + 16 + qc];
        float2 s2_24 = *(const float2*)&s2s[j0 + 16 + qc + 8];
        uint32_t Af[2][4];
        Af[0][0] = pcvt(s1v0, s2_0,  m[0], lacc0);
        Af[0][1] = pcvt(s1v1, s2_0,  m[2], lacc1);
        Af[0][2] = pcvt(s1v0, s2_8,  m[1], lacc0);
        Af[0][3] = pcvt(s1v1, s2_8,  m[3], lacc1);
        Af[1][0] = pcvt(s1v0, s2_16, m[4], lacc0);
        Af[1][1] = pcvt(s1v1, s2_16, m[6], lacc1);
        Af[1][2] = pcvt(s1v0, s2_24, m[5], lacc0);
        Af[1][3] = pcvt(s1v1, s2_24, m[7], lacc1);

        // ---- prefetch adj for tile+1 (latency hidden under MMA + sync)
        if (more) {
            const int jn = (tile + 1) * JT;
            const int* p0 = adjr0 + jn + qc;
            const int* p1 = adjr1 + jn + qc;
            m[0] = *(const int2*)(p0);      m[1] = *(const int2*)(p0 + 8);
            m[2] = *(const int2*)(p1);      m[3] = *(const int2*)(p1 + 8);
            m[4] = *(const int2*)(p0 + 16); m[5] = *(const int2*)(p0 + 24);
            m[6] = *(const int2*)(p1 + 16); m[7] = *(const int2*)(p1 + 24);
        }

        // ---- MMA: warp = m16 x n64 x k32, 1 term
        const uint32_t b0a = smem_u32(sm + OFF_B(cur) + bn_l * BSTR + bk_l);
#pragma unroll
        for (int kt = 0; kt < 2; ++kt) {
#pragma unroll
            for (int np = 0; np < 4; ++np) {
                uint32_t bh0, bh1, bh2, bh3;
                ldsm_x4(bh0, bh1, bh2, bh3, b0a + (uint32_t)(np * 16) * ROWB + kt * 32);
                mma_f16(c[2 * np],     Af[kt], bh0, bh1);
                mma_f16(c[2 * np + 1], Af[kt], bh2, bh3);
            }
        }

        // ---- store B next
        if (more) *(uint4*)(sm + OFF_B(nb) + bn * BSTR + bk) = bnext;
        __syncthreads();
    }

    // l row sums: reduce over the 4 quad lanes (scaled by 2^-8 -> undo)
    lacc0 += __shfl_xor_sync(0xffffffffu, lacc0, 1);
    lacc0 += __shfl_xor_sync(0xffffffffu, lacc0, 2);
    lacc1 += __shfl_xor_sync(0xffffffffu, lacc1, 1);
    lacc1 += __shfl_xor_sync(0xffffffffu, lacc1, 2);
    if ((lid & 3) == 0) {
        g_lp[(size_t)split * NN + r0] = lacc0 * 256.f;
        g_lp[(size_t)split * NN + r1] = lacc1 * 256.f;
    }

    // ---- epilogue: raw partials (undo 2^-8 scale)
    const int rbase = i0 + wid * 16 + qr;
    const int cbase = qc;
#pragma unroll
    for (int nt = 0; nt < 8; ++nt) {
        const int col = nt * 8 + cbase;
        float* d0 = &g_part[((size_t)split * NN + rbase) * OUTD + col];
        float* d1 = &g_part[((size_t)split * NN + rbase + 8) * OUTD + col];
        *(float2*)d0 = make_float2(c[nt][0] * 256.f, c[nt][1] * 256.f);
        *(float2*)d1 = make_float2(c[nt][2] * 256.f, c[nt][3] * 256.f);
    }
}

// ---------------------------------------------------------------------------
// K3: reduce NSPLIT partials, normalize, ELU.
// ---------------------------------------------------------------------------
__global__ __launch_bounds__(128) void k3_reduce(float* __restrict__ out) {
    const int q   = blockIdx.x * 128 + threadIdx.x;
    const int row = q >> 4;
    const int c4  = (q & 15) * 4;

    float l = 0.f;
#pragma unroll
    for (int s = 0; s < NSPLIT; ++s) l += g_lp[(size_t)s * NN + row];
    const float inv = 1.0f / l;

    float4 acc = make_float4(0.f, 0.f, 0.f, 0.f);
#pragma unroll
    for (int s = 0; s < NSPLIT; ++s) {
        float4 v = *(const float4*)&g_part[((size_t)s * NN + row) * OUTD + c4];
        acc.x += v.x; acc.y += v.y; acc.z += v.z; acc.w += v.w;
    }
    acc.x *= inv; acc.y *= inv; acc.z *= inv; acc.w *= inv;
    acc.x = acc.x > 0.f ? acc.x : expm1f(acc.x);
    acc.y = acc.y > 0.f ? acc.y : expm1f(acc.y);
    acc.z = acc.z > 0.f ? acc.z : expm1f(acc.z);
    acc.w = acc.w > 0.f ? acc.w : expm1f(acc.w);
    *(float4*)&out[(size_t)row * OUTD + c4] = acc;
}

extern "C" void kernel_launch(void* const* d_in, const int* in_sizes, int n_in,
                              void* d_out, int out_size) {
    const float* x   = (const float*)d_in[0];
    const int*   adj = (const int*)d_in[1];
    const float* W   = (const float*)d_in[2];
    const float* a   = (const float*)d_in[3];
    float* out = (float*)d_out;

    cudaFuncSetAttribute(k2_attn_mma, cudaFuncAttributeMaxDynamicSharedMemorySize, SMEM_BYTES);

    k1_proj<<<256, 128>>>(x, W, a);
    k1b_transpose<<<NN / 64, 256>>>();
    k2_attn_mma<<<dim3(NN / ITILE, NSPLIT), 256, SMEM_BYTES>>>(adj);
    k3_reduce<<<(NN * OUTD / 4) / 128, 128>>>(out);
}